// round 1
// baseline (speedup 1.0000x reference)
#include <cuda_runtime.h>

// ColBERT MaxSim:
//   scores[b,c] = sum_n max_s dot(qs[b,n,:], ps[c,s,:])
// qs: (64, 32, 128) fp32, ps: (64, 1024, 128) fp32, out: (64, 64) fp32.

#define NQ 64
#define ND 64
#define TQ 32      // query tokens
#define TP 1024    // doc tokens
#define DIM 128
#define CHUNK 256      // doc tokens per smem tile
#define PSTRIDE 129    // padded row stride (floats): 32*129 % 32 == 0, lane stride 129 % 32 == 1 -> conflict-free
#define TN 4           // n-rows per thread
#define TS 8           // s-cols per thread
#define NTHREADS 256

__global__ __launch_bounds__(NTHREADS, 1)
void colbert_maxsim_kernel(const float* __restrict__ qs,
                           const float* __restrict__ ps,
                           float* __restrict__ out) {
    extern __shared__ float smem[];
    float* q_s = smem;                  // [TQ][DIM]
    float* p_s = smem + TQ * DIM;       // [CHUNK][PSTRIDE]
    __shared__ float warp_part[NTHREADS / 32];

    const int b = blockIdx.y;
    const int c = blockIdx.x;
    const int tid = threadIdx.x;
    const int lane = tid & 31;
    const int wid = tid >> 5;           // warp id == n-group (8 warps x 4 rows = 32 n)
    const int n0 = wid * TN;

    // Load the full q tile once (coalesced float4).
    {
        const float4* qg = (const float4*)(qs + (size_t)b * TQ * DIM);
        float4* q4 = (float4*)q_s;
        #pragma unroll
        for (int i = tid; i < TQ * DIM / 4; i += NTHREADS) q4[i] = qg[i];
    }

    float mx[TN];
    #pragma unroll
    for (int i = 0; i < TN; i++) mx[i] = -1e30f;

    const float* pg = ps + (size_t)c * TP * DIM;

    for (int s0 = 0; s0 < TP; s0 += CHUNK) {
        __syncthreads();  // protect previous chunk's reads (and first-iter q fill ordering)
        // Stage p chunk: CHUNK x DIM floats, padded rows.
        {
            const float4* pg4 = (const float4*)(pg + (size_t)s0 * DIM);
            #pragma unroll
            for (int i = tid; i < CHUNK * DIM / 4; i += NTHREADS) {
                int s  = i >> 5;            // i / (DIM/4)
                int dd = (i & 31) << 2;     // (i % (DIM/4)) * 4
                float4 v = pg4[i];
                float* dst = p_s + s * PSTRIDE + dd;
                dst[0] = v.x; dst[1] = v.y; dst[2] = v.z; dst[3] = v.w;
            }
        }
        __syncthreads();

        // Register-tiled 32n x 256s sim block; thread owns (n0..n0+3) x (lane + 32j).
        float acc[TN][TS];
        #pragma unroll
        for (int i = 0; i < TN; i++)
            #pragma unroll
            for (int j = 0; j < TS; j++) acc[i][j] = 0.0f;

        const float* prow = p_s + lane * PSTRIDE;
        #pragma unroll 4
        for (int d = 0; d < DIM; d++) {
            float qv[TN];
            #pragma unroll
            for (int i = 0; i < TN; i++) qv[i] = q_s[(n0 + i) * DIM + d];  // broadcast
            float pv[TS];
            #pragma unroll
            for (int j = 0; j < TS; j++) pv[j] = prow[j * 32 * PSTRIDE + d];  // conflict-free
            #pragma unroll
            for (int i = 0; i < TN; i++)
                #pragma unroll
                for (int j = 0; j < TS; j++)
                    acc[i][j] = fmaf(qv[i], pv[j], acc[i][j]);
        }

        #pragma unroll
        for (int i = 0; i < TN; i++)
            #pragma unroll
            for (int j = 0; j < TS; j++)
                mx[i] = fmaxf(mx[i], acc[i][j]);
    }

    // Max over the 32 lanes (s dimension) -- each warp exclusively owns its 4 n-rows.
    #pragma unroll
    for (int i = 0; i < TN; i++) {
        float v = mx[i];
        #pragma unroll
        for (int o = 16; o; o >>= 1) v = fmaxf(v, __shfl_xor_sync(0xffffffffu, v, o));
        mx[i] = v;
    }
    if (lane == 0)
        warp_part[wid] = mx[0] + mx[1] + mx[2] + mx[3];
    __syncthreads();
    if (tid == 0) {
        float s = 0.0f;
        #pragma unroll
        for (int w = 0; w < NTHREADS / 32; w++) s += warp_part[w];
        out[b * ND + c] = s;
    }
}

extern "C" void kernel_launch(void* const* d_in, const int* in_sizes, int n_in,
                              void* d_out, int out_size) {
    const float* qs = (const float*)d_in[0];   // (64, 32, 128) fp32
    const float* ps = (const float*)d_in[1];   // (64, 1024, 128) fp32
    float* out = (float*)d_out;                // (64, 64) fp32

    size_t smem_bytes = (size_t)(TQ * DIM + CHUNK * PSTRIDE) * sizeof(float);
    cudaFuncSetAttribute(colbert_maxsim_kernel,
                         cudaFuncAttributeMaxDynamicSharedMemorySize,
                         (int)smem_bytes);
    dim3 grid(ND, NQ);
    colbert_maxsim_kernel<<<grid, NTHREADS, smem_bytes>>>(qs, ps, out);
}

// round 3
// speedup vs baseline: 10.5599x; 10.5599x over previous
#include <cuda_runtime.h>
#include <cuda_bf16.h>
#include <cstdint>

// ColBERT MaxSim via mma.sync bf16 HMMA (arch-agnostic tensor path).
//   scores[b,c] = sum_n max_s dot(qs[b,n,:], ps[c,s,:])
// qs: (64,32,128) fp32, ps: (64,1024,128) fp32, out: (64,64) fp32.
//
// Kernel 1: grid (64 c, 2 half). CTA stages p[c, half*512 .. +512, :] as bf16 (padded),
// loops 16 A-tiles of 128 q-rows (rows = b*32+n), computes 128x512 sim with HMMA,
// folds max over the 512 cols, writes part[(c,half), qrow].
// Kernel 2: max over halves, warp-sum over n.

#define DIM 128
#define PSTR 136          // padded bf16 row stride (272 B = 17 x 16B -> ldmatrix conflict-free)
#define ROWB 272          // bytes per padded row
#define HALF_TOK 512
#define QROWS 2048        // 64 b * 32 n
#define NTILES 16
#define NTHREADS 256

#define P_OFF 0
#define A_OFF (HALF_TOK * ROWB)            // 139264
#define SM_TOTAL (A_OFF + 128 * ROWB)      // 174080

__device__ float g_part[64 * 2 * QROWS];

__device__ __forceinline__ uint32_t smem_u32(const void* p) {
    uint32_t a;
    asm("{ .reg .u64 t; cvta.to.shared.u64 t, %1; cvt.u32.u64 %0, t; }" : "=r"(a) : "l"(p));
    return a;
}

#define LDSM_X4(r, addr) \
    asm volatile("ldmatrix.sync.aligned.m8n8.x4.shared.b16 {%0,%1,%2,%3}, [%4];" \
                 : "=r"((r)[0]), "=r"((r)[1]), "=r"((r)[2]), "=r"((r)[3]) : "r"(addr))

#define MMA_16816(d, a, b) \
    asm volatile("mma.sync.aligned.m16n8k16.row.col.f32.bf16.bf16.f32 " \
                 "{%0,%1,%2,%3}, {%4,%5,%6,%7}, {%8,%9}, {%0,%1,%2,%3};" \
                 : "+f"((d)[0]), "+f"((d)[1]), "+f"((d)[2]), "+f"((d)[3]) \
                 : "r"((a)[0]), "r"((a)[1]), "r"((a)[2]), "r"((a)[3]), \
                   "r"((b)[0]), "r"((b)[1]))

// Convert a ROWS x 128 fp32 row-major tile into bf16 padded smem (stride PSTR).
template<int ROWS>
__device__ __forceinline__ void stage_bf16(char* sm_dst, const float* __restrict__ src) {
    const int tid = threadIdx.x;
    #pragma unroll
    for (int i = tid; i < ROWS * 16; i += NTHREADS) {
        int row = i >> 4;
        int c8  = (i & 15) << 3;
        const float4* s4 = reinterpret_cast<const float4*>(src + row * DIM + c8);
        float4 v0 = s4[0];
        float4 v1 = s4[1];
        __nv_bfloat162 b0 = __floats2bfloat162_rn(v0.x, v0.y);
        __nv_bfloat162 b1 = __floats2bfloat162_rn(v0.z, v0.w);
        __nv_bfloat162 b2 = __floats2bfloat162_rn(v1.x, v1.y);
        __nv_bfloat162 b3 = __floats2bfloat162_rn(v1.z, v1.w);
        uint4 packed;
        packed.x = *reinterpret_cast<uint32_t*>(&b0);
        packed.y = *reinterpret_cast<uint32_t*>(&b1);
        packed.z = *reinterpret_cast<uint32_t*>(&b2);
        packed.w = *reinterpret_cast<uint32_t*>(&b3);
        *reinterpret_cast<uint4*>(sm_dst + row * ROWB + c8 * 2) = packed;
    }
}

__global__ __launch_bounds__(NTHREADS, 1)
void colbert_hmma_kernel(const float* __restrict__ qs,
                         const float* __restrict__ ps,
                         float* __restrict__ part) {
    extern __shared__ char sm[];
    __shared__ float s_red[2][128];

    const int c = blockIdx.x;
    const int half = blockIdx.y;
    const int tid = threadIdx.x;
    const int lane = tid & 31;
    const int wid = tid >> 5;
    const int wr = wid & 3;    // row group: rows [wr*32, +32)
    const int wc = wid >> 2;   // col group within 64-col n-block

    const uint32_t smem_base = smem_u32(sm);
    const uint32_t p_base = smem_base + P_OFF;
    const uint32_t a_base = smem_base + A_OFF;

    // Stage the 512-token p half once.
    const float* pg = ps + ((size_t)c * 1024 + (size_t)half * HALF_TOK) * DIM;
    stage_bf16<HALF_TOK>(sm + P_OFF, pg);

    // Precomputed ldmatrix lane addressing.
    const uint32_t a_lane_off = (uint32_t)((lane & 15) * ROWB + (lane >> 4) * 16);
    const int bgrp = lane >> 3;
    const uint32_t b_lane_off = (uint32_t)(((bgrp >> 1) * 8 + (lane & 7)) * ROWB + (bgrp & 1) * 16);

    #pragma unroll 1
    for (int t = 0; t < NTILES; t++) {
        __syncthreads();   // previous epilogue / A reads done
        stage_bf16<128>(sm + A_OFF, qs + (size_t)t * 128 * DIM);
        __syncthreads();

        // Hoist A fragments for this tile: 2 m-tiles x 8 k-steps x 4 regs.
        uint32_t af[2][8][4];
        #pragma unroll
        for (int mt = 0; mt < 2; mt++) {
            #pragma unroll
            for (int ks = 0; ks < 8; ks++) {
                uint32_t addr = a_base + (uint32_t)((wr * 32 + mt * 16) * ROWB + ks * 32)
                              + a_lane_off;
                LDSM_X4(af[mt][ks], addr);
            }
        }

        float rm[2][2] = {{-3.0e38f, -3.0e38f}, {-3.0e38f, -3.0e38f}};

        #pragma unroll 1
        for (int nb = 0; nb < 8; nb++) {
            const int col0 = nb * 64 + wc * 32;
            float acc[2][4][4];
            #pragma unroll
            for (int mt = 0; mt < 2; mt++)
                #pragma unroll
                for (int nt = 0; nt < 4; nt++)
                    #pragma unroll
                    for (int i = 0; i < 4; i++) acc[mt][nt][i] = 0.0f;

            #pragma unroll
            for (int ks = 0; ks < 8; ks++) {
                uint32_t bf[4][2];
                uint32_t b0 = p_base + (uint32_t)(col0 * ROWB + ks * 32) + b_lane_off;
                uint32_t r[4];
                LDSM_X4(r, b0);
                bf[0][0] = r[0]; bf[0][1] = r[1]; bf[1][0] = r[2]; bf[1][1] = r[3];
                LDSM_X4(r, b0 + 16 * ROWB);
                bf[2][0] = r[0]; bf[2][1] = r[1]; bf[3][0] = r[2]; bf[3][1] = r[3];
                #pragma unroll
                for (int mt = 0; mt < 2; mt++)
                    #pragma unroll
                    for (int nt = 0; nt < 4; nt++)
                        MMA_16816(acc[mt][nt], af[mt][ks], bf[nt]);
            }

            #pragma unroll
            for (int mt = 0; mt < 2; mt++)
                #pragma unroll
                for (int nt = 0; nt < 4; nt++) {
                    rm[mt][0] = fmaxf(rm[mt][0], fmaxf(acc[mt][nt][0], acc[mt][nt][1]));
                    rm[mt][1] = fmaxf(rm[mt][1], fmaxf(acc[mt][nt][2], acc[mt][nt][3]));
                }
        }

        // Reduce across the 4 lanes sharing each row (lane%4 = col index).
        #pragma unroll
        for (int mt = 0; mt < 2; mt++)
            #pragma unroll
            for (int h = 0; h < 2; h++) {
                float v = rm[mt][h];
                v = fmaxf(v, __shfl_xor_sync(0xffffffffu, v, 1));
                v = fmaxf(v, __shfl_xor_sync(0xffffffffu, v, 2));
                if ((lane & 3) == 0)
                    s_red[wc][wr * 32 + mt * 16 + h * 8 + (lane >> 2)] = v;
            }
        __syncthreads();
        if (tid < 128) {
            float v = fmaxf(s_red[0][tid], s_red[1][tid]);
            part[((size_t)c * 2 + half) * QROWS + t * 128 + tid] = v;
        }
    }
}

__global__ __launch_bounds__(256, 4)
void colbert_combine_kernel(const float* __restrict__ part, float* __restrict__ out) {
    int idx = blockIdx.x * blockDim.x + threadIdx.x;   // 0 .. 64*64*32-1
    int n = idx & 31;
    int c = (idx >> 5) & 63;
    int b = idx >> 11;
    int qrow = b * 32 + n;
    float m = fmaxf(part[((size_t)c * 2 + 0) * QROWS + qrow],
                    part[((size_t)c * 2 + 1) * QROWS + qrow]);
    #pragma unroll
    for (int o = 16; o; o >>= 1) m += __shfl_xor_sync(0xffffffffu, m, o);
    if (n == 0) out[b * 64 + c] = m;
}

extern "C" void kernel_launch(void* const* d_in, const int* in_sizes, int n_in,
                              void* d_out, int out_size) {
    const float* qs = (const float*)d_in[0];   // (64, 32, 128)
    const float* ps = (const float*)d_in[1];   // (64, 1024, 128)
    float* out = (float*)d_out;                // (64, 64)

    float* part;
    cudaGetSymbolAddress((void**)&part, g_part);

    cudaFuncSetAttribute(colbert_hmma_kernel,
                         cudaFuncAttributeMaxDynamicSharedMemorySize, SM_TOTAL);
    dim3 grid(64, 2);
    colbert_hmma_kernel<<<grid, NTHREADS, SM_TOTAL>>>(qs, ps, part);
    colbert_combine_kernel<<<(64 * 64 * 32) / 256, 256>>>(part, out);
}

// round 4
// speedup vs baseline: 11.4240x; 1.0818x over previous
#include <cuda_runtime.h>
#include <cuda_bf16.h>
#include <cstdint>

// ColBERT MaxSim via mma.sync bf16 HMMA.
//   scores[b,c] = sum_n max_s dot(qs[b,n,:], ps[c,s,:])
// qs: (64,32,128) fp32, ps: (64,1024,128) fp32, out: (64,64) fp32.
//
// Kernel 0: convert qs -> bf16 global scratch (rows of 128 bf16, contiguous).
// Kernel 1: grid (64 c, 2 half). CTA stages p[c, half*512.., :] as bf16 (padded) once,
//   loops 16 A-tiles of 128 q-rows (cp.async from bf16 scratch, double-buffered),
//   computes 128x512 sim with HMMA, folds max over cols, writes part[(c,half), qrow].
// Kernel 2: max over halves, warp-sum over n.

#define DIM 128
#define ROWB 272          // padded bf16 row: 136 bf16 = 272 B = 17 x 16B -> ldmatrix conflict-free
#define HALF_TOK 512
#define QROWS 2048        // 64 b * 32 n
#define NTILES 16
#define NTHREADS 256

#define P_OFF 0
#define A_OFF  (HALF_TOK * ROWB)            // 139264
#define A_SZ   (128 * ROWB)                 // 34816
#define SM_TOTAL (A_OFF + 2 * A_SZ)         // 208896

__device__ float g_part[64 * 2 * QROWS];
__device__ __nv_bfloat16 g_qbf[QROWS * DIM];

__device__ __forceinline__ uint32_t smem_u32(const void* p) {
    uint32_t a;
    asm("{ .reg .u64 t; cvta.to.shared.u64 t, %1; cvt.u32.u64 %0, t; }" : "=r"(a) : "l"(p));
    return a;
}

#define LDSM_X4(r, addr) \
    asm volatile("ldmatrix.sync.aligned.m8n8.x4.shared.b16 {%0,%1,%2,%3}, [%4];" \
                 : "=r"((r)[0]), "=r"((r)[1]), "=r"((r)[2]), "=r"((r)[3]) : "r"(addr))

#define MMA_16816(d, a, b) \
    asm volatile("mma.sync.aligned.m16n8k16.row.col.f32.bf16.bf16.f32 " \
                 "{%0,%1,%2,%3}, {%4,%5,%6,%7}, {%8,%9}, {%0,%1,%2,%3};" \
                 : "+f"((d)[0]), "+f"((d)[1]), "+f"((d)[2]), "+f"((d)[3]) \
                 : "r"((a)[0]), "r"((a)[1]), "r"((a)[2]), "r"((a)[3]), \
                   "r"((b)[0]), "r"((b)[1]))

#define CP_ASYNC16(dst, src) \
    asm volatile("cp.async.cg.shared.global [%0], [%1], 16;" :: "r"(dst), "l"(src) : "memory")
#define CP_COMMIT()  asm volatile("cp.async.commit_group;" ::: "memory")
#define CP_WAIT0()   asm volatile("cp.async.wait_group 0;" ::: "memory")

// Convert a ROWS x 128 fp32 row-major tile into bf16 padded smem (stride ROWB bytes).
template<int ROWS>
__device__ __forceinline__ void stage_bf16(char* sm_dst, const float* __restrict__ src) {
    const int tid = threadIdx.x;
    #pragma unroll
    for (int i = tid; i < ROWS * 16; i += NTHREADS) {
        int row = i >> 4;
        int c8  = (i & 15) << 3;
        const float4* s4 = reinterpret_cast<const float4*>(src + row * DIM + c8);
        float4 v0 = s4[0];
        float4 v1 = s4[1];
        __nv_bfloat162 b0 = __floats2bfloat162_rn(v0.x, v0.y);
        __nv_bfloat162 b1 = __floats2bfloat162_rn(v0.z, v0.w);
        __nv_bfloat162 b2 = __floats2bfloat162_rn(v1.x, v1.y);
        __nv_bfloat162 b3 = __floats2bfloat162_rn(v1.z, v1.w);
        uint4 packed;
        packed.x = *reinterpret_cast<uint32_t*>(&b0);
        packed.y = *reinterpret_cast<uint32_t*>(&b1);
        packed.z = *reinterpret_cast<uint32_t*>(&b2);
        packed.w = *reinterpret_cast<uint32_t*>(&b3);
        *reinterpret_cast<uint4*>(sm_dst + row * ROWB + c8 * 2) = packed;
    }
}

// Async-stage a 128 x 128 bf16 tile (contiguous 256B rows) into padded smem.
__device__ __forceinline__ void stage_A_async(uint32_t a_dst, const __nv_bfloat16* src) {
    const int tid = threadIdx.x;
    #pragma unroll
    for (int i = tid; i < 128 * 16; i += NTHREADS) {
        int row = i >> 4;
        int cb  = (i & 15) << 4;   // byte col
        CP_ASYNC16(a_dst + row * ROWB + cb,
                   reinterpret_cast<const char*>(src) + row * 256 + cb);
    }
}

__global__ __launch_bounds__(256, 4)
void convert_q_kernel(const float* __restrict__ qs, __nv_bfloat16* __restrict__ qbf) {
    int i = blockIdx.x * blockDim.x + threadIdx.x;   // one per 8 elems; 32768 threads
    const float4* s4 = reinterpret_cast<const float4*>(qs) + i * 2;
    float4 v0 = s4[0];
    float4 v1 = s4[1];
    __nv_bfloat162 b0 = __floats2bfloat162_rn(v0.x, v0.y);
    __nv_bfloat162 b1 = __floats2bfloat162_rn(v0.z, v0.w);
    __nv_bfloat162 b2 = __floats2bfloat162_rn(v1.x, v1.y);
    __nv_bfloat162 b3 = __floats2bfloat162_rn(v1.z, v1.w);
    uint4 packed;
    packed.x = *reinterpret_cast<uint32_t*>(&b0);
    packed.y = *reinterpret_cast<uint32_t*>(&b1);
    packed.z = *reinterpret_cast<uint32_t*>(&b2);
    packed.w = *reinterpret_cast<uint32_t*>(&b3);
    reinterpret_cast<uint4*>(qbf)[i] = packed;
}

__global__ __launch_bounds__(NTHREADS, 1)
void colbert_hmma_kernel(const __nv_bfloat16* __restrict__ qbf,
                         const float* __restrict__ ps,
                         float* __restrict__ part) {
    extern __shared__ char sm[];
    __shared__ float s_red[2][128];

    const int c = blockIdx.x;
    const int half = blockIdx.y;
    const int tid = threadIdx.x;
    const int lane = tid & 31;
    const int wid = tid >> 5;
    const int wr = wid & 3;    // row group: rows [wr*32, +32)
    const int wc = wid >> 2;   // col group within 64-col n-block

    const uint32_t smem_base = smem_u32(sm);
    const uint32_t p_base = smem_base + P_OFF;
    const uint32_t a_base = smem_base + A_OFF;

    // Kick off A tile 0 (async), then stage the 512-token p half (fp32 -> bf16).
    stage_A_async(a_base, qbf);
    CP_COMMIT();
    const float* pg = ps + ((size_t)c * 1024 + (size_t)half * HALF_TOK) * DIM;
    stage_bf16<HALF_TOK>(sm + P_OFF, pg);

    // ldmatrix lane addressing.
    const uint32_t a_lane_off = (uint32_t)((lane & 15) * ROWB + (lane >> 4) * 16);
    const int bgrp = lane >> 3;
    const uint32_t b_lane_off = (uint32_t)(((bgrp >> 1) * 8 + (lane & 7)) * ROWB + (bgrp & 1) * 16);

    #pragma unroll 1
    for (int t = 0; t < NTILES; t++) {
        const uint32_t abuf = a_base + (uint32_t)(t & 1) * A_SZ;

        CP_WAIT0();        // A[t] landed (this thread's copies)
        __syncthreads();   // everyone's copies visible; prev epilogue reads done

        // Hoist A fragments: 2 m-tiles x 8 k-steps x 4 regs.
        uint32_t af[2][8][4];
        #pragma unroll
        for (int mt = 0; mt < 2; mt++) {
            #pragma unroll
            for (int ks = 0; ks < 8; ks++) {
                uint32_t addr = abuf + (uint32_t)((wr * 32 + mt * 16) * ROWB + ks * 32)
                              + a_lane_off;
                LDSM_X4(af[mt][ks], addr);
            }
        }

        // Prefetch A[t+1] into the other buffer (completes under the compute loop).
        if (t + 1 < NTILES) {
            stage_A_async(a_base + (uint32_t)((t + 1) & 1) * A_SZ,
                          qbf + (size_t)(t + 1) * 128 * DIM);
        }
        CP_COMMIT();

        float rm[2][2] = {{-3.0e38f, -3.0e38f}, {-3.0e38f, -3.0e38f}};

        #pragma unroll 1
        for (int nb = 0; nb < 8; nb++) {
            const int col0 = nb * 64 + wc * 32;
            float acc[2][4][4];
            #pragma unroll
            for (int mt = 0; mt < 2; mt++)
                #pragma unroll
                for (int nt = 0; nt < 4; nt++)
                    #pragma unroll
                    for (int i = 0; i < 4; i++) acc[mt][nt][i] = 0.0f;

            #pragma unroll
            for (int ks = 0; ks < 8; ks++) {
                uint32_t bf[4][2];
                uint32_t b0 = p_base + (uint32_t)(col0 * ROWB + ks * 32) + b_lane_off;
                uint32_t r[4];
                LDSM_X4(r, b0);
                bf[0][0] = r[0]; bf[0][1] = r[1]; bf[1][0] = r[2]; bf[1][1] = r[3];
                LDSM_X4(r, b0 + 16 * ROWB);
                bf[2][0] = r[0]; bf[2][1] = r[1]; bf[3][0] = r[2]; bf[3][1] = r[3];
                #pragma unroll
                for (int mt = 0; mt < 2; mt++)
                    #pragma unroll
                    for (int nt = 0; nt < 4; nt++)
                        MMA_16816(acc[mt][nt], af[mt][ks], bf[nt]);
            }

            #pragma unroll
            for (int mt = 0; mt < 2; mt++)
                #pragma unroll
                for (int nt = 0; nt < 4; nt++) {
                    rm[mt][0] = fmaxf(rm[mt][0], fmaxf(acc[mt][nt][0], acc[mt][nt][1]));
                    rm[mt][1] = fmaxf(rm[mt][1], fmaxf(acc[mt][nt][2], acc[mt][nt][3]));
                }
        }

        // Reduce across the 4 lanes sharing each row (lane%4 = col index).
        #pragma unroll
        for (int mt = 0; mt < 2; mt++)
            #pragma unroll
            for (int h = 0; h < 2; h++) {
                float v = rm[mt][h];
                v = fmaxf(v, __shfl_xor_sync(0xffffffffu, v, 1));
                v = fmaxf(v, __shfl_xor_sync(0xffffffffu, v, 2));
                if ((lane & 3) == 0)
                    s_red[wc][wr * 32 + mt * 16 + h * 8 + (lane >> 2)] = v;
            }
        __syncthreads();
        if (tid < 128) {
            float v = fmaxf(s_red[0][tid], s_red[1][tid]);
            part[((size_t)c * 2 + half) * QROWS + t * 128 + tid] = v;
        }
    }
}

__global__ __launch_bounds__(256, 4)
void colbert_combine_kernel(const float* __restrict__ part, float* __restrict__ out) {
    int idx = blockIdx.x * blockDim.x + threadIdx.x;   // 0 .. 64*64*32-1
    int n = idx & 31;
    int c = (idx >> 5) & 63;
    int b = idx >> 11;
    int qrow = b * 32 + n;
    float m = fmaxf(part[((size_t)c * 2 + 0) * QROWS + qrow],
                    part[((size_t)c * 2 + 1) * QROWS + qrow]);
    #pragma unroll
    for (int o = 16; o; o >>= 1) m += __shfl_xor_sync(0xffffffffu, m, o);
    if (n == 0) out[b * 64 + c] = m;
}

extern "C" void kernel_launch(void* const* d_in, const int* in_sizes, int n_in,
                              void* d_out, int out_size) {
    const float* qs = (const float*)d_in[0];   // (64, 32, 128)
    const float* ps = (const float*)d_in[1];   // (64, 1024, 128)
    float* out = (float*)d_out;                // (64, 64)

    float* part;
    cudaGetSymbolAddress((void**)&part, g_part);
    __nv_bfloat16* qbf;
    cudaGetSymbolAddress((void**)&qbf, g_qbf);

    convert_q_kernel<<<(QROWS * DIM / 8) / 256, 256>>>(qs, qbf);

    cudaFuncSetAttribute(colbert_hmma_kernel,
                         cudaFuncAttributeMaxDynamicSharedMemorySize, SM_TOTAL);
    dim3 grid(64, 2);
    colbert_hmma_kernel<<<grid, NTHREADS, SM_TOTAL>>>(qbf, ps, part);
    colbert_combine_kernel<<<(64 * 64 * 32) / 256, 256>>>(part, out);
}